// round 11
// baseline (speedup 1.0000x reference)
#include <cuda_runtime.h>
#include <math.h>
#include <stddef.h>

#define N_NODE 40000
#define EMB    100
#define CH     25        // float4 chunks per embedding row
#define B      512
#define L      50
#define NN     50
#define E_EDGES 800000

// ---- scratch: device globals, referenced ONLY from device code -------------
__device__ __align__(16) float g_x1[N_NODE * EMB];
__device__ __align__(16) float g_x2[N_NODE * EMB];
__device__ __align__(16) float g_e1t[(N_NODE + 1) * EMB];  // row0 zeros, 1.. = emb_gnn
__device__ __align__(16) float g_h[B * NN * EMB];
__device__ __align__(16) float g_seq[B * L * EMB];
__device__ __align__(16) float g_hs[B * EMB];
__device__ __align__(16) float g_sel[B * EMB];
__device__ __align__(16) float g_s1[B * EMB];
__device__ __align__(16) float g_s2[B * EMB];
__device__ __align__(16) float g_self[B * EMB];
__device__ float g_lse[B];

__device__ __forceinline__ float wredsum(float v) {
    #pragma unroll
    for (int o = 16; o; o >>= 1) v += __shfl_xor_sync(0xffffffffu, v, o);
    return v;
}
__device__ __forceinline__ float wredmax(float v) {
    #pragma unroll
    for (int o = 16; o; o >>= 1) v = fmaxf(v, __shfl_xor_sync(0xffffffffu, v, o));
    return v;
}

// ---------------- 0. zero SpMM accumulators + e1t row 0 ----------------------
__global__ void k_zero() {
    int i = blockIdx.x * blockDim.x + threadIdx.x;
    if (i < N_NODE * EMB) { g_x1[i] = 0.f; g_x2[i] = 0.f; }
    if (i < EMB) g_e1t[i] = 0.f;
}

// ---------------- 1. SpMM layer 1: g_x1[rows[e]] += vals[e]*nemb[cols[e]] ----
// NOTE: g_x1/g_x2 are referenced in device code (NOT passed from host —
// host-side addresses of __device__ globals are invalid and on GB300 (ATS)
// silently resolve to host shadow memory; that was the bug in R2-R9).
__global__ void k_spmm1(const float* __restrict__ in,
                        const int* __restrict__ rows, const int* __restrict__ cols,
                        const float* __restrict__ vals) {
    int idx = blockIdx.x * blockDim.x + threadIdx.x;
    if (idx >= E_EDGES * CH) return;
    int e = idx / CH, c = idx % CH;
    int r = rows[e], cl = cols[e];
    float v = vals[e];
    float4 x = ((const float4*)in)[cl * CH + c];
    float* dst = g_x1 + (r * CH + c) * 4;
    atomicAdd(dst + 0, x.x * v);
    atomicAdd(dst + 1, x.y * v);
    atomicAdd(dst + 2, x.z * v);
    atomicAdd(dst + 3, x.w * v);
}

// ---------------- 2. SpMM layer 2: g_x2[rows[e]] += vals[e]*g_x1[cols[e]] ----
__global__ void k_spmm2(const int* __restrict__ rows, const int* __restrict__ cols,
                        const float* __restrict__ vals) {
    int idx = blockIdx.x * blockDim.x + threadIdx.x;
    if (idx >= E_EDGES * CH) return;
    int e = idx / CH, c = idx % CH;
    int r = rows[e], cl = cols[e];
    float v = vals[e];
    float4 x = ((const float4*)g_x1)[cl * CH + c];
    float* dst = g_x2 + (r * CH + c) * 4;
    atomicAdd(dst + 0, x.x * v);
    atomicAdd(dst + 1, x.y * v);
    atomicAdd(dst + 2, x.z * v);
    atomicAdd(dst + 3, x.w * v);
}

// ---------------- 3. per-node l2norm + weighted sum -> e1t[1..] --------------
__global__ void k_combine_item(const float* __restrict__ emb, const float* __restrict__ bw) {
    int wid  = (blockIdx.x * blockDim.x + threadIdx.x) >> 5;
    int lane = threadIdx.x & 31;
    if (wid >= N_NODE) return;
    float4 a = {0.f,0.f,0.f,0.f}, bb = a, cc = a;
    if (lane < CH) {
        a  = ((const float4*)emb )[wid * CH + lane];
        bb = ((const float4*)g_x1)[wid * CH + lane];
        cc = ((const float4*)g_x2)[wid * CH + lane];
    }
    float s0 = a.x*a.x + a.y*a.y + a.z*a.z + a.w*a.w;
    float s1 = bb.x*bb.x + bb.y*bb.y + bb.z*bb.z + bb.w*bb.w;
    float s2 = cc.x*cc.x + cc.y*cc.y + cc.z*cc.z + cc.w*cc.w;
    s0 = wredsum(s0); s1 = wredsum(s1); s2 = wredsum(s2);
    float i0 = bw[0] / fmaxf(sqrtf(s0), 1e-12f);
    float i1 = bw[1] / fmaxf(sqrtf(s1), 1e-12f);
    float i2 = bw[2] / fmaxf(sqrtf(s2), 1e-12f);
    if (lane < CH) {
        float4 r;
        r.x = a.x*i0 + bb.x*i1 + cc.x*i2;
        r.y = a.y*i0 + bb.y*i1 + cc.y*i2;
        r.z = a.z*i0 + bb.z*i1 + cc.z*i2;
        r.w = a.w*i0 + bb.w*i1 + cc.w*i2;
        ((float4*)g_e1t)[(wid + 1) * CH + lane] = r;
    }
}

// ---------------- 4. GAT per batch element -----------------------------------
__global__ void k_gat(const int* __restrict__ items, const int* __restrict__ adj,
                      const float* __restrict__ a0, const float* __restrict__ a1,
                      const float* __restrict__ a2, const float* __restrict__ a3) {
    __shared__ float sh[NN][EMB];
    __shared__ float sa[4][EMB];
    __shared__ float se[NN][NN];
    __shared__ int   sit[NN];
    int b = blockIdx.x, t = threadIdx.x, nt = blockDim.x;
    for (int i = t; i < NN; i += nt) sit[i] = items[b * NN + i];
    for (int i = t; i < EMB; i += nt) {
        sa[0][i] = a0[i]; sa[1][i] = a1[i]; sa[2][i] = a2[i]; sa[3][i] = a3[i];
    }
    __syncthreads();
    for (int p = t; p < NN * EMB; p += nt)
        sh[p / EMB][p % EMB] = g_e1t[sit[p / EMB] * EMB + p % EMB];
    __syncthreads();
    for (int p = t; p < NN * NN; p += nt) {
        int i = p / NN, j = p % NN;
        int av = adj[b * NN * NN + p];
        float ev;
        if (av >= 1 && av <= 4) {
            const float* ak = sa[av - 1];
            float acc = 0.f;
            #pragma unroll 4
            for (int d = 0; d < EMB; d++) acc += sh[i][d] * ak[d] * sh[j][d];
            ev = acc > 0.f ? acc : 0.2f * acc;
        } else ev = -9e15f;
        se[i][j] = ev;
    }
    __syncthreads();
    int w = t >> 5, lane = t & 31, nw = nt >> 5;
    for (int i = w; i < NN; i += nw) {
        float m = -INFINITY;
        for (int j = lane; j < NN; j += 32) m = fmaxf(m, se[i][j]);
        m = wredmax(m);
        float s = 0.f;
        for (int j = lane; j < NN; j += 32) { float ex = expf(se[i][j] - m); se[i][j] = ex; s += ex; }
        s = wredsum(s);
        float inv = 1.f / s;
        for (int j = lane; j < NN; j += 32) se[i][j] *= inv;
    }
    __syncthreads();
    for (int p = t; p < NN * EMB; p += nt) {
        int i = p / EMB, d = p % EMB;
        float acc = 0.f;
        #pragma unroll 5
        for (int j = 0; j < NN; j++) acc += se[i][j] * sh[j][d];
        g_h[b * NN * EMB + p] = acc;
    }
}

// ---------------- 5. get_seq + hs ---------------------------------------------
__global__ void k_seq(const int* __restrict__ rev, const int* __restrict__ alias,
                      const float* __restrict__ slen) {
    __shared__ float ss[L][EMB];
    int b = blockIdx.x, t = threadIdx.x, nt = blockDim.x;
    for (int p = t; p < L * EMB; p += nt) {
        int l = p / EMB, d = p % EMB;
        int r  = rev[b * L + l];
        int al = alias[b * L + l];
        float v = 0.2f * g_e1t[r * EMB + d] + 0.8f * g_h[(b * NN + al) * EMB + d];
        ss[l][d] = v;
        g_seq[b * L * EMB + p] = v;
    }
    __syncthreads();
    float sl = slen[b];
    for (int d = t; d < EMB; d += nt) {
        float a = 0.f;
        #pragma unroll 5
        for (int l = 0; l < L; l++) a += ss[l][d];
        g_hs[b * EMB + d] = a / sl;
    }
}

// ---------------- 6. soft attention -> sel ------------------------------------
__global__ void k_attn(const float* __restrict__ w1W, const float* __restrict__ w1b,
                       const float* __restrict__ g1W, const float* __restrict__ g1b,
                       const float* __restrict__ g2W, const float* __restrict__ w2,
                       const float* __restrict__ pos, const int* __restrict__ mask) {
    __shared__ float ss[L][EMB];
    __shared__ float snh[L][EMB];
    __shared__ float sgh[EMB];
    __shared__ float shsv[EMB];
    __shared__ float sbeta[L];
    int b = blockIdx.x, t = threadIdx.x, nt = blockDim.x;
    for (int p = t; p < L * EMB; p += nt) ss[p / EMB][p % EMB] = g_seq[b * L * EMB + p];
    for (int d = t; d < EMB; d += nt) shsv[d] = g_hs[b * EMB + d];
    for (int l = t; l < L; l += nt) sbeta[l] = 0.f;
    __syncthreads();
    for (int o = t; o < EMB; o += nt) {
        float acc = 0.f;
        #pragma unroll 4
        for (int d = 0; d < EMB; d++) acc += shsv[d] * g2W[o * EMB + d];
        sgh[o] = acc;
    }
    for (int p = t; p < L * EMB; p += nt) {
        int l = p / EMB, o = p % EMB;
        float acc = w1b[o];
        const float* wr = w1W + o * 2 * EMB;
        #pragma unroll 4
        for (int k = 0; k < EMB; k++) acc += pos[l * EMB + k] * wr[k];
        #pragma unroll 4
        for (int k = 0; k < EMB; k++) acc += ss[l][k] * wr[EMB + k];
        snh[l][o] = tanhf(acc);
    }
    __syncthreads();
    for (int p = t; p < L * EMB; p += nt) {
        int l = p / EMB, o = p % EMB;
        float acc = g1b[o] + sgh[o];
        const float* wr = g1W + o * EMB;
        #pragma unroll 4
        for (int k = 0; k < EMB; k++) acc += snh[l][k] * wr[k];
        float s = 1.f / (1.f + expf(-acc));
        atomicAdd(&sbeta[l], s * w2[o]);
    }
    __syncthreads();
    for (int l = t; l < L; l += nt) sbeta[l] *= (float)mask[b * L + l];
    __syncthreads();
    for (int d = t; d < EMB; d += nt) {
        float acc = 0.f;
        #pragma unroll 5
        for (int l = 0; l < L; l++) acc += sbeta[l] * ss[l][d];
        g_sel[b * EMB + d] = acc;
    }
}

// ---------------- 7. session conv (hardwired globals) -------------------------
__global__ void k_sessmm1(const float* __restrict__ A) {
    __shared__ float sadj[B];
    int b = blockIdx.x, t = threadIdx.x, nt = blockDim.x;
    for (int j = t; j < B; j += nt) sadj[j] = A[b * B + j];
    __syncthreads();
    for (int d = t; d < EMB; d += nt) {
        float acc = 0.f;
        #pragma unroll 4
        for (int j = 0; j < B; j++) acc += sadj[j] * g_sel[j * EMB + d];
        g_s1[b * EMB + d] = acc;
    }
}
__global__ void k_sessmm2(const float* __restrict__ A) {
    __shared__ float sadj[B];
    int b = blockIdx.x, t = threadIdx.x, nt = blockDim.x;
    for (int j = t; j < B; j += nt) sadj[j] = A[b * B + j];
    __syncthreads();
    for (int d = t; d < EMB; d += nt) {
        float acc = 0.f;
        #pragma unroll 4
        for (int j = 0; j < B; j++) acc += sadj[j] * g_s1[j * EMB + d];
        g_s2[b * EMB + d] = acc;
    }
}

__global__ void k_combine_sess(const float* __restrict__ aw) {
    int wid  = (blockIdx.x * blockDim.x + threadIdx.x) >> 5;
    int lane = threadIdx.x & 31;
    if (wid >= B) return;
    float4 a = {0.f,0.f,0.f,0.f}, bb = a, cc = a;
    if (lane < CH) {
        a  = ((const float4*)g_sel)[wid * CH + lane];
        bb = ((const float4*)g_s1 )[wid * CH + lane];
        cc = ((const float4*)g_s2 )[wid * CH + lane];
    }
    float s0 = a.x*a.x + a.y*a.y + a.z*a.z + a.w*a.w;
    float s1 = bb.x*bb.x + bb.y*bb.y + bb.z*bb.z + bb.w*bb.w;
    float s2 = cc.x*cc.x + cc.y*cc.y + cc.z*cc.z + cc.w*cc.w;
    s0 = wredsum(s0); s1 = wredsum(s1); s2 = wredsum(s2);
    float i0 = aw[0] / fmaxf(sqrtf(s0), 1e-12f);
    float i1 = aw[1] / fmaxf(sqrtf(s1), 1e-12f);
    float i2 = aw[2] / fmaxf(sqrtf(s2), 1e-12f);
    if (lane < CH) {
        float4 r;
        r.x = a.x*i0 + bb.x*i1 + cc.x*i2;
        r.y = a.y*i0 + bb.y*i1 + cc.y*i2;
        r.z = a.z*i0 + bb.z*i1 + cc.z*i2;
        r.w = a.w*i0 + bb.w*i1 + cc.w*i2;
        ((float4*)g_self)[wid * CH + lane] = r;
    }
}

// ---------------- 8. scores = 4 * self @ emb_gnn.T ----------------------------
#define SBT 32
#define SNT 64
__global__ void k_scores(float* __restrict__ sc) {
    __shared__ float sA[SBT][EMB + 1];
    __shared__ float sB[SNT][EMB + 1];
    int bn = blockIdx.x * SNT;
    int bb = blockIdx.y * SBT;
    int t = threadIdx.x;
    for (int p = t; p < SBT * EMB; p += 256) {
        int r = p / EMB, c = p % EMB;
        sA[r][c] = 4.f * g_self[(bb + r) * EMB + c];
    }
    for (int p = t; p < SNT * EMB; p += 256) {
        int r = p / EMB, c = p % EMB;
        sB[r][c] = g_e1t[(bn + r + 1) * EMB + c];
    }
    __syncthreads();
    int tx = t & 15, ty = t >> 4;
    float acc[2][4] = {};
    #pragma unroll 4
    for (int k = 0; k < EMB; k++) {
        float a0 = sA[ty][k], a1 = sA[ty + 16][k];
        float b0 = sB[tx][k], b1 = sB[tx + 16][k], b2 = sB[tx + 32][k], b3 = sB[tx + 48][k];
        acc[0][0] += a0 * b0; acc[0][1] += a0 * b1; acc[0][2] += a0 * b2; acc[0][3] += a0 * b3;
        acc[1][0] += a1 * b0; acc[1][1] += a1 * b1; acc[1][2] += a1 * b2; acc[1][3] += a1 * b3;
    }
    #pragma unroll
    for (int i = 0; i < 2; i++)
        #pragma unroll
        for (int j = 0; j < 4; j++)
            sc[(size_t)(bb + ty + i * 16) * N_NODE + bn + tx + j * 16] = acc[i][j];
}

// ---------------- 9. per-row log-sum-exp --------------------------------------
__global__ void k_lse(const float* __restrict__ sc) {
    int b = blockIdx.x, t = threadIdx.x, nt = blockDim.x;
    const float* row = sc + (size_t)b * N_NODE;
    float m = -INFINITY;
    for (int n = t; n < N_NODE; n += nt) m = fmaxf(m, row[n]);
    m = wredmax(m);
    __shared__ float sm[8];
    if ((t & 31) == 0) sm[t >> 5] = m;
    __syncthreads();
    float mm = sm[0];
    for (int w = 1; w < (nt >> 5); w++) mm = fmaxf(mm, sm[w]);
    float s = 0.f;
    for (int n = t; n < N_NODE; n += nt) s += expf(row[n] - mm);
    s = wredsum(s);
    __shared__ float ssum[8];
    if ((t & 31) == 0) ssum[t >> 5] = s;
    __syncthreads();
    if (t == 0) {
        float tot = 0.f;
        for (int w = 0; w < (nt >> 5); w++) tot += ssum[w];
        g_lse[b] = mm + logf(tot);
    }
}

// ---------------- 10. loss -----------------------------------------------------
__global__ void k_loss(const float* __restrict__ sc, const int* __restrict__ tar,
                       float* __restrict__ out, int off) {
    int t = threadIdx.x;  // 512 threads == B
    float v = sc[(size_t)t * N_NODE + tar[t]] - g_lse[t];
    v = wredsum(v);
    __shared__ float sp[16];
    if ((t & 31) == 0) sp[t >> 5] = v;
    __syncthreads();
    if (t == 0) {
        float tot = 0.f;
        for (int w = 0; w < 16; w++) tot += sp[w];
        float loss = -tot / (float)B;
        if (off >= 2)      { out[0] = 0.f; out[1] = loss; }
        else if (off == 1) { out[0] = loss; }
    }
}

// ---------------- host launcher ------------------------------------------------
extern "C" void kernel_launch(void* const* d_in, const int* in_sizes, int n_in,
                              void* d_out, int out_size) {
    int sh = (n_in >= 6 && in_sizes[5] == 1) ? 0 : -1;

    const int*   tar   = (const int*  )d_in[0];
    const int*   rev   = (const int*  )d_in[1];
    const int*   mask  = (const int*  )d_in[2];
    const float* slen  = (const float*)d_in[3];
    const float* sadj  = (const float*)d_in[4];
    const int*   items = (const int*  )d_in[6 + sh];
    const int*   adj   = (const int*  )d_in[7 + sh];
    const int*   alias = (const int*  )d_in[8 + sh];
    const int*   rows  = (const int*  )d_in[9 + sh];
    const int*   cols  = (const int*  )d_in[10 + sh];
    const float* vals  = (const float*)d_in[11 + sh];
    const float* nemb  = (const float*)d_in[12 + sh];
    const float* bit   = (const float*)d_in[13 + sh];
    const float* asess = (const float*)d_in[14 + sh];
    const float* a0    = (const float*)d_in[15 + sh];
    const float* a1    = (const float*)d_in[16 + sh];
    const float* a2    = (const float*)d_in[17 + sh];
    const float* a3    = (const float*)d_in[18 + sh];
    const float* w1W   = (const float*)d_in[19 + sh];
    const float* w1b   = (const float*)d_in[20 + sh];
    const float* w2    = (const float*)d_in[21 + sh];
    const float* g1W   = (const float*)d_in[22 + sh];
    const float* g1b   = (const float*)d_in[23 + sh];
    const float* g2W   = (const float*)d_in[24 + sh];
    const float* pos   = (const float*)d_in[25 + sh];

    float* outf = (float*)d_out;
    int off = out_size - B * N_NODE;
    if (off < 0) off = 0;
    float* scores = outf + off;

    k_zero<<<(N_NODE * EMB + 255) / 256, 256>>>();
    k_spmm1<<<(E_EDGES * CH + 255) / 256, 256>>>(nemb, rows, cols, vals);
    k_spmm2<<<(E_EDGES * CH + 255) / 256, 256>>>(rows, cols, vals);
    k_combine_item<<<(N_NODE * 32 + 255) / 256, 256>>>(nemb, bit);
    k_gat<<<B, 256>>>(items, adj, a0, a1, a2, a3);
    k_seq<<<B, 128>>>(rev, alias, slen);
    k_attn<<<B, 256>>>(w1W, w1b, g1W, g1b, g2W, w2, pos, mask);
    k_sessmm1<<<B, 128>>>(sadj);
    k_sessmm2<<<B, 128>>>(sadj);
    k_combine_sess<<<(B * 32 + 255) / 256, 256>>>(asess);
    k_scores<<<dim3(N_NODE / SNT, B / SBT), 256>>>(scores);
    k_lse<<<B, 256>>>(scores);
    k_loss<<<1, 512>>>(scores, tar, outf, off);
}

// round 12
// speedup vs baseline: 3.8582x; 3.8582x over previous
#include <cuda_runtime.h>
#include <math.h>
#include <stddef.h>

#define N_NODE 40000
#define EMB    100
#define CH     25        // float4 chunks per embedding row
#define B      512
#define L      50
#define NN     50
#define E_EDGES 800000

// ---- scratch: device globals, referenced ONLY from device code -------------
__device__ __align__(16) float g_x1[N_NODE * EMB];
__device__ __align__(16) float g_x2[N_NODE * EMB];
__device__ __align__(16) float g_e1t[(N_NODE + 1) * EMB];  // row0 zeros, 1.. = emb_gnn
__device__ __align__(16) float g_h[B * NN * EMB];
__device__ __align__(16) float g_seq[B * L * EMB];
__device__ __align__(16) float g_hs[B * EMB];
__device__ __align__(16) float g_posw[L * EMB];            // pos@w1W[:, :100].T + w1b
__device__ __align__(16) float g_sel[B * EMB];
__device__ __align__(16) float g_s1[B * EMB];
__device__ __align__(16) float g_s2[B * EMB];
__device__ __align__(16) float g_self[B * EMB];
__device__ float g_lse[B];

__device__ __forceinline__ float wredsum(float v) {
    #pragma unroll
    for (int o = 16; o; o >>= 1) v += __shfl_xor_sync(0xffffffffu, v, o);
    return v;
}
__device__ __forceinline__ float wredmax(float v) {
    #pragma unroll
    for (int o = 16; o; o >>= 1) v = fmaxf(v, __shfl_xor_sync(0xffffffffu, v, o));
    return v;
}

// ---------------- 0. zero SpMM accumulators + e1t row 0 ----------------------
__global__ void k_zero() {
    int i = blockIdx.x * blockDim.x + threadIdx.x;
    if (i < N_NODE * EMB) { g_x1[i] = 0.f; g_x2[i] = 0.f; }
    if (i < EMB) g_e1t[i] = 0.f;
}

// ---------------- 1. SpMM layer 1 (vector red: validated R2==R3) -------------
__global__ void k_spmm1(const float* __restrict__ in,
                        const int* __restrict__ rows, const int* __restrict__ cols,
                        const float* __restrict__ vals) {
    int idx = blockIdx.x * blockDim.x + threadIdx.x;
    if (idx >= E_EDGES * CH) return;
    int e = idx / CH, c = idx % CH;
    int r = rows[e], cl = cols[e];
    float v = vals[e];
    float4 x = ((const float4*)in)[cl * CH + c];
    float4* dst = ((float4*)g_x1) + r * CH + c;
    asm volatile("red.global.add.v4.f32 [%0], {%1,%2,%3,%4};"
                 :: "l"(dst), "f"(x.x * v), "f"(x.y * v), "f"(x.z * v), "f"(x.w * v)
                 : "memory");
}

// ---------------- 2. SpMM layer 2 --------------------------------------------
__global__ void k_spmm2(const int* __restrict__ rows, const int* __restrict__ cols,
                        const float* __restrict__ vals) {
    int idx = blockIdx.x * blockDim.x + threadIdx.x;
    if (idx >= E_EDGES * CH) return;
    int e = idx / CH, c = idx % CH;
    int r = rows[e], cl = cols[e];
    float v = vals[e];
    float4 x = ((const float4*)g_x1)[cl * CH + c];
    float4* dst = ((float4*)g_x2) + r * CH + c;
    asm volatile("red.global.add.v4.f32 [%0], {%1,%2,%3,%4};"
                 :: "l"(dst), "f"(x.x * v), "f"(x.y * v), "f"(x.z * v), "f"(x.w * v)
                 : "memory");
}

// ---------------- 3. per-node l2norm + weighted sum -> e1t[1..] --------------
__global__ void k_combine_item(const float* __restrict__ emb, const float* __restrict__ bw) {
    int wid  = (blockIdx.x * blockDim.x + threadIdx.x) >> 5;
    int lane = threadIdx.x & 31;
    if (wid >= N_NODE) return;
    float4 a = {0.f,0.f,0.f,0.f}, bb = a, cc = a;
    if (lane < CH) {
        a  = ((const float4*)emb )[wid * CH + lane];
        bb = ((const float4*)g_x1)[wid * CH + lane];
        cc = ((const float4*)g_x2)[wid * CH + lane];
    }
    float s0 = a.x*a.x + a.y*a.y + a.z*a.z + a.w*a.w;
    float s1 = bb.x*bb.x + bb.y*bb.y + bb.z*bb.z + bb.w*bb.w;
    float s2 = cc.x*cc.x + cc.y*cc.y + cc.z*cc.z + cc.w*cc.w;
    s0 = wredsum(s0); s1 = wredsum(s1); s2 = wredsum(s2);
    float i0 = bw[0] / fmaxf(sqrtf(s0), 1e-12f);
    float i1 = bw[1] / fmaxf(sqrtf(s1), 1e-12f);
    float i2 = bw[2] / fmaxf(sqrtf(s2), 1e-12f);
    if (lane < CH) {
        float4 r;
        r.x = a.x*i0 + bb.x*i1 + cc.x*i2;
        r.y = a.y*i0 + bb.y*i1 + cc.y*i2;
        r.z = a.z*i0 + bb.z*i1 + cc.z*i2;
        r.w = a.w*i0 + bb.w*i1 + cc.w*i2;
        ((float4*)g_e1t)[(wid + 1) * CH + lane] = r;
    }
}

// ---------------- 4. posw[l][o] = pos[l] . w1W[o, :100] + w1b[o] -------------
__global__ void k_posw(const float* __restrict__ pos, const float* __restrict__ w1W,
                       const float* __restrict__ w1b) {
    int gw   = (blockIdx.x * blockDim.x + threadIdx.x) >> 5;
    int lane = threadIdx.x & 31;
    if (gw >= L * EMB) return;
    int l = gw / EMB, o = gw % EMB;
    const float* wr = w1W + o * 2 * EMB;
    float acc = 0.f;
    for (int k = lane; k < EMB; k += 32) acc += pos[l * EMB + k] * wr[k];
    acc = wredsum(acc);
    if (lane == 0) g_posw[l * EMB + o] = acc + w1b[o];
}

// ---------------- 5. GAT per batch element (padded shared) -------------------
__global__ void k_gat(const int* __restrict__ items, const int* __restrict__ adj,
                      const float* __restrict__ a0, const float* __restrict__ a1,
                      const float* __restrict__ a2, const float* __restrict__ a3) {
    __shared__ float sh[NN][EMB + 1];   // pad: stride 101 -> conflict-free
    __shared__ float sa[4][EMB + 1];
    __shared__ float se[NN][NN];
    __shared__ int   sit[NN];
    int b = blockIdx.x, t = threadIdx.x, nt = blockDim.x;
    for (int i = t; i < NN; i += nt) sit[i] = items[b * NN + i];
    for (int i = t; i < EMB; i += nt) {
        sa[0][i] = a0[i]; sa[1][i] = a1[i]; sa[2][i] = a2[i]; sa[3][i] = a3[i];
    }
    __syncthreads();
    for (int p = t; p < NN * EMB; p += nt)
        sh[p / EMB][p % EMB] = g_e1t[sit[p / EMB] * EMB + p % EMB];
    __syncthreads();
    for (int p = t; p < NN * NN; p += nt) {
        int i = p / NN, j = p % NN;
        int av = adj[b * NN * NN + p];
        float ev;
        if (av >= 1 && av <= 4) {
            const float* ak = sa[av - 1];
            float acc = 0.f;
            #pragma unroll 4
            for (int d = 0; d < EMB; d++) acc += sh[i][d] * ak[d] * sh[j][d];
            ev = acc > 0.f ? acc : 0.2f * acc;
        } else ev = -9e15f;
        se[i][j] = ev;
    }
    __syncthreads();
    int w = t >> 5, lane = t & 31, nw = nt >> 5;
    for (int i = w; i < NN; i += nw) {
        float m = -INFINITY;
        for (int j = lane; j < NN; j += 32) m = fmaxf(m, se[i][j]);
        m = wredmax(m);
        float s = 0.f;
        for (int j = lane; j < NN; j += 32) { float ex = expf(se[i][j] - m); se[i][j] = ex; s += ex; }
        s = wredsum(s);
        float inv = 1.f / s;
        for (int j = lane; j < NN; j += 32) se[i][j] *= inv;
    }
    __syncthreads();
    for (int p = t; p < NN * EMB; p += nt) {
        int i = p / EMB, d = p % EMB;
        float acc = 0.f;
        #pragma unroll 5
        for (int j = 0; j < NN; j++) acc += se[i][j] * sh[j][d];
        g_h[b * NN * EMB + p] = acc;
    }
}

// ---------------- 6. get_seq + hs ---------------------------------------------
__global__ void k_seq(const int* __restrict__ rev, const int* __restrict__ alias,
                      const float* __restrict__ slen) {
    __shared__ float ss[L][EMB];
    int b = blockIdx.x, t = threadIdx.x, nt = blockDim.x;
    for (int p = t; p < L * EMB; p += nt) {
        int l = p / EMB, d = p % EMB;
        int r  = rev[b * L + l];
        int al = alias[b * L + l];
        float v = 0.2f * g_e1t[r * EMB + d] + 0.8f * g_h[(b * NN + al) * EMB + d];
        ss[l][d] = v;
        g_seq[b * L * EMB + p] = v;
    }
    __syncthreads();
    float sl = slen[b];
    for (int d = t; d < EMB; d += nt) {
        float a = 0.f;
        #pragma unroll 5
        for (int l = 0; l < L; l++) a += ss[l][d];
        g_hs[b * EMB + d] = a / sl;
    }
}

// ---------------- 7. soft attention -> sel (broadcast-friendly mapping) ------
__global__ void k_attn(const float* __restrict__ w1W,
                       const float* __restrict__ g1W, const float* __restrict__ g1b,
                       const float* __restrict__ g2W, const float* __restrict__ w2,
                       const int* __restrict__ mask) {
    __shared__ float ss [L][EMB + 1];   // padded: lane-l access conflict-free
    __shared__ float snh[L][EMB + 1];
    __shared__ float sgh[EMB];
    __shared__ float shsv[EMB];
    __shared__ float sbeta[L];
    int b = blockIdx.x, t = threadIdx.x, nt = blockDim.x;
    int w = t >> 5, lane = t & 31, nw = nt >> 5;
    for (int p = t; p < L * EMB; p += nt) ss[p / EMB][p % EMB] = g_seq[b * L * EMB + p];
    for (int d = t; d < EMB; d += nt) shsv[d] = g_hs[b * EMB + d];
    for (int l = t; l < L; l += nt) sbeta[l] = 0.f;
    __syncthreads();
    // glu2 term: warp per output row -> coalesced g2W reads
    for (int o = w; o < EMB; o += nw) {
        float acc = 0.f;
        for (int d = lane; d < EMB; d += 32) acc += shsv[d] * g2W[o * EMB + d];
        acc = wredsum(acc);
        if (lane == 0) sgh[o] = acc;
    }
    // nh1: p -> (o = p/L, l = p%L): weight rows broadcast within warp
    for (int p = t; p < L * EMB; p += nt) {
        int o = p / L, l = p % L;
        const float* wr = w1W + o * 2 * EMB + EMB;   // second half (seq part)
        float acc = g_posw[l * EMB + o];
        #pragma unroll 4
        for (int k = 0; k < EMB; k++) acc += ss[l][k] * wr[k];
        snh[l][o] = tanhf(acc);
    }
    __syncthreads();
    // nh2 + beta accumulation
    for (int p = t; p < L * EMB; p += nt) {
        int o = p / L, l = p % L;
        float acc = g1b[o] + sgh[o];
        const float* wr = g1W + o * EMB;
        #pragma unroll 4
        for (int k = 0; k < EMB; k++) acc += snh[l][k] * wr[k];
        float s = 1.f / (1.f + expf(-acc));
        atomicAdd(&sbeta[l], s * w2[o]);
    }
    __syncthreads();
    for (int l = t; l < L; l += nt) sbeta[l] *= (float)mask[b * L + l];
    __syncthreads();
    for (int d = t; d < EMB; d += nt) {
        float acc = 0.f;
        #pragma unroll 5
        for (int l = 0; l < L; l++) acc += sbeta[l] * ss[l][d];
        g_sel[b * EMB + d] = acc;
    }
}

// ---------------- 8. session conv (hardwired globals) -------------------------
__global__ void k_sessmm1(const float* __restrict__ A) {
    __shared__ float sadj[B];
    int b = blockIdx.x, t = threadIdx.x, nt = blockDim.x;
    for (int j = t; j < B; j += nt) sadj[j] = A[b * B + j];
    __syncthreads();
    for (int d = t; d < EMB; d += nt) {
        float acc = 0.f;
        #pragma unroll 4
        for (int j = 0; j < B; j++) acc += sadj[j] * g_sel[j * EMB + d];
        g_s1[b * EMB + d] = acc;
    }
}
__global__ void k_sessmm2(const float* __restrict__ A) {
    __shared__ float sadj[B];
    int b = blockIdx.x, t = threadIdx.x, nt = blockDim.x;
    for (int j = t; j < B; j += nt) sadj[j] = A[b * B + j];
    __syncthreads();
    for (int d = t; d < EMB; d += nt) {
        float acc = 0.f;
        #pragma unroll 4
        for (int j = 0; j < B; j++) acc += sadj[j] * g_s1[j * EMB + d];
        g_s2[b * EMB + d] = acc;
    }
}

__global__ void k_combine_sess(const float* __restrict__ aw) {
    int wid  = (blockIdx.x * blockDim.x + threadIdx.x) >> 5;
    int lane = threadIdx.x & 31;
    if (wid >= B) return;
    float4 a = {0.f,0.f,0.f,0.f}, bb = a, cc = a;
    if (lane < CH) {
        a  = ((const float4*)g_sel)[wid * CH + lane];
        bb = ((const float4*)g_s1 )[wid * CH + lane];
        cc = ((const float4*)g_s2 )[wid * CH + lane];
    }
    float s0 = a.x*a.x + a.y*a.y + a.z*a.z + a.w*a.w;
    float s1 = bb.x*bb.x + bb.y*bb.y + bb.z*bb.z + bb.w*bb.w;
    float s2 = cc.x*cc.x + cc.y*cc.y + cc.z*cc.z + cc.w*cc.w;
    s0 = wredsum(s0); s1 = wredsum(s1); s2 = wredsum(s2);
    float i0 = aw[0] / fmaxf(sqrtf(s0), 1e-12f);
    float i1 = aw[1] / fmaxf(sqrtf(s1), 1e-12f);
    float i2 = aw[2] / fmaxf(sqrtf(s2), 1e-12f);
    if (lane < CH) {
        float4 r;
        r.x = a.x*i0 + bb.x*i1 + cc.x*i2;
        r.y = a.y*i0 + bb.y*i1 + cc.y*i2;
        r.z = a.z*i0 + bb.z*i1 + cc.z*i2;
        r.w = a.w*i0 + bb.w*i1 + cc.w*i2;
        ((float4*)g_self)[wid * CH + lane] = r;
    }
}

// ---------------- 9. scores = 4 * self @ emb_gnn.T ----------------------------
#define SBT 32
#define SNT 64
__global__ void k_scores(float* __restrict__ sc) {
    __shared__ float sA[SBT][EMB + 1];
    __shared__ float sB[SNT][EMB + 1];
    int bn = blockIdx.x * SNT;
    int bb = blockIdx.y * SBT;
    int t = threadIdx.x;
    for (int p = t; p < SBT * EMB; p += 256) {
        int r = p / EMB, c = p % EMB;
        sA[r][c] = 4.f * g_self[(bb + r) * EMB + c];
    }
    for (int p = t; p < SNT * EMB; p += 256) {
        int r = p / EMB, c = p % EMB;
        sB[r][c] = g_e1t[(bn + r + 1) * EMB + c];
    }
    __syncthreads();
    int tx = t & 15, ty = t >> 4;
    float acc[2][4] = {};
    #pragma unroll 4
    for (int k = 0; k < EMB; k++) {
        float a0 = sA[ty][k], a1 = sA[ty + 16][k];
        float b0 = sB[tx][k], b1 = sB[tx + 16][k], b2 = sB[tx + 32][k], b3 = sB[tx + 48][k];
        acc[0][0] += a0 * b0; acc[0][1] += a0 * b1; acc[0][2] += a0 * b2; acc[0][3] += a0 * b3;
        acc[1][0] += a1 * b0; acc[1][1] += a1 * b1; acc[1][2] += a1 * b2; acc[1][3] += a1 * b3;
    }
    #pragma unroll
    for (int i = 0; i < 2; i++)
        #pragma unroll
        for (int j = 0; j < 4; j++)
            sc[(size_t)(bb + ty + i * 16) * N_NODE + bn + tx + j * 16] = acc[i][j];
}

// ---------------- 10. per-row log-sum-exp --------------------------------------
__global__ void k_lse(const float* __restrict__ sc) {
    int b = blockIdx.x, t = threadIdx.x, nt = blockDim.x;
    const float* row = sc + (size_t)b * N_NODE;
    float m = -INFINITY;
    for (int n = t; n < N_NODE; n += nt) m = fmaxf(m, row[n]);
    m = wredmax(m);
    __shared__ float sm[8];
    if ((t & 31) == 0) sm[t >> 5] = m;
    __syncthreads();
    float mm = sm[0];
    for (int w = 1; w < (nt >> 5); w++) mm = fmaxf(mm, sm[w]);
    float s = 0.f;
    for (int n = t; n < N_NODE; n += nt) s += expf(row[n] - mm);
    s = wredsum(s);
    __shared__ float ssum[8];
    if ((t & 31) == 0) ssum[t >> 5] = s;
    __syncthreads();
    if (t == 0) {
        float tot = 0.f;
        for (int w = 0; w < (nt >> 5); w++) tot += ssum[w];
        g_lse[b] = mm + logf(tot);
    }
}

// ---------------- 11. loss -----------------------------------------------------
__global__ void k_loss(const float* __restrict__ sc, const int* __restrict__ tar,
                       float* __restrict__ out, int off) {
    int t = threadIdx.x;  // 512 threads == B
    float v = sc[(size_t)t * N_NODE + tar[t]] - g_lse[t];
    v = wredsum(v);
    __shared__ float sp[16];
    if ((t & 31) == 0) sp[t >> 5] = v;
    __syncthreads();
    if (t == 0) {
        float tot = 0.f;
        for (int w = 0; w < 16; w++) tot += sp[w];
        float loss = -tot / (float)B;
        if (off >= 2)      { out[0] = 0.f; out[1] = loss; }
        else if (off == 1) { out[0] = loss; }
    }
}

// ---------------- host launcher ------------------------------------------------
extern "C" void kernel_launch(void* const* d_in, const int* in_sizes, int n_in,
                              void* d_out, int out_size) {
    int sh = (n_in >= 6 && in_sizes[5] == 1) ? 0 : -1;

    const int*   tar   = (const int*  )d_in[0];
    const int*   rev   = (const int*  )d_in[1];
    const int*   mask  = (const int*  )d_in[2];
    const float* slen  = (const float*)d_in[3];
    const float* sadj  = (const float*)d_in[4];
    const int*   items = (const int*  )d_in[6 + sh];
    const int*   adj   = (const int*  )d_in[7 + sh];
    const int*   alias = (const int*  )d_in[8 + sh];
    const int*   rows  = (const int*  )d_in[9 + sh];
    const int*   cols  = (const int*  )d_in[10 + sh];
    const float* vals  = (const float*)d_in[11 + sh];
    const float* nemb  = (const float*)d_in[12 + sh];
    const float* bit   = (const float*)d_in[13 + sh];
    const float* asess = (const float*)d_in[14 + sh];
    const float* a0    = (const float*)d_in[15 + sh];
    const float* a1    = (const float*)d_in[16 + sh];
    const float* a2    = (const float*)d_in[17 + sh];
    const float* a3    = (const float*)d_in[18 + sh];
    const float* w1W   = (const float*)d_in[19 + sh];
    const float* w1b   = (const float*)d_in[20 + sh];
    const float* w2    = (const float*)d_in[21 + sh];
    const float* g1W   = (const float*)d_in[22 + sh];
    const float* g1b   = (const float*)d_in[23 + sh];
    const float* g2W   = (const float*)d_in[24 + sh];
    const float* pos   = (const float*)d_in[25 + sh];

    float* outf = (float*)d_out;
    int off = out_size - B * N_NODE;
    if (off < 0) off = 0;
    float* scores = outf + off;

    k_zero<<<(N_NODE * EMB + 255) / 256, 256>>>();
    k_spmm1<<<(E_EDGES * CH + 255) / 256, 256>>>(nemb, rows, cols, vals);
    k_spmm2<<<(E_EDGES * CH + 255) / 256, 256>>>(rows, cols, vals);
    k_combine_item<<<(N_NODE * 32 + 255) / 256, 256>>>(nemb, bit);
    k_posw<<<(L * EMB * 32 + 255) / 256, 256>>>(pos, w1W, w1b);
    k_gat<<<B, 256>>>(items, adj, a0, a1, a2, a3);
    k_seq<<<B, 128>>>(rev, alias, slen);
    k_attn<<<B, 256>>>(w1W, g1W, g1b, g2W, w2, mask);
    k_sessmm1<<<B, 128>>>(sadj);
    k_sessmm2<<<B, 128>>>(sadj);
    k_combine_sess<<<(B * 32 + 255) / 256, 256>>>(asess);
    k_scores<<<dim3(N_NODE / SNT, B / SBT), 256>>>(scores);
    k_lse<<<B, 256>>>(scores);
    k_loss<<<1, 512>>>(scores, tar, outf, off);
}